// round 6
// baseline (speedup 1.0000x reference)
#include <cuda_runtime.h>

// Geometry constants (match reference)
#define HN 512
#define WN 512
#define NA 720
#define ND 725
#define NT 768
#define PW 514                  // padded width/height (1-px zero border each side)
#define PAD_ELEMS (PW * PW)

// Scratch: padded image and padded transpose (allocation-free __device__ globals)
__device__ float g_imgP[PAD_ELEMS];
__device__ float g_imgPT[PAD_ELEMS];

// Build padded img = x + reco, its transpose, and copy reco to output tail.
__global__ void prep_kernel(const float* __restrict__ x,
                            const float* __restrict__ reco,
                            float* __restrict__ out_reco) {
    int i = blockIdx.x * blockDim.x + threadIdx.x;
    if (i >= PAD_ELEMS) return;
    int v = i / PW;
    int u = i - v * PW;
    float val = 0.0f;
    if (u >= 1 && u <= WN && v >= 1 && v <= HN) {
        int src = (v - 1) * WN + (u - 1);
        val = x[src] + reco[src];
    }
    g_imgP[i] = val;
    g_imgPT[u * PW + v] = val;   // imgPT[(x+1)*PW + (y+1)] = img[y][x]
    if (i < HN * WN) out_reco[i] = reco[i];
}

// One thread per (angle, detector). March along the ray, bilinear-sample,
// accumulate. Layout (img vs imgT) chosen per angle so lane-to-lane motion
// is mostly along the contiguous dimension.
__global__ void __launch_bounds__(128) proj_kernel(float* __restrict__ sino) {
    const int a = blockIdx.y;
    const int d = blockIdx.x * blockDim.x + threadIdx.x;
    const int dd = min(d, ND - 1);           // keep full warps active for redux

    const float theta = (float)a * (float)(3.14159265358979323846 / 720.0);
    float sn, c;
    sincosf(theta, &sn, &c);

    const float s = (float)dd - 362.0f;      // (ND-1)/2 = 362
    // sample point: x(t) = s*c - t*sn + 255.5 ; y(t) = s*sn + t*c + 255.5
    const float bx = fmaf(s, c, 255.5f);
    const float by = fmaf(s, sn, 255.5f);

    const float* __restrict__ buf;
    float bu, bv, du, dv;
    if (fabsf(sn) > fabsf(c)) {              // detector axis mostly vertical -> transpose
        buf = g_imgPT; bu = by; du = c;  bv = bx; dv = -sn;
    } else {
        buf = g_imgP;  bu = bx; du = -sn; bv = by; dv = c;
    }

    // Clip t to where any bilinear tap can be nonzero: fu,fv in (-1, 512).
    float t0 = -1e9f, t1 = 1e9f;
    if (fabsf(du) > 1e-8f) {
        float ta = (-1.0f - bu) / du;
        float tb = (512.0f - bu) / du;
        t0 = fmaxf(t0, fminf(ta, tb));
        t1 = fminf(t1, fmaxf(ta, tb));
    } else if (bu <= -1.0f || bu >= 512.0f) {
        t0 = 1e9f;                            // empty
    }
    if (fabsf(dv) > 1e-8f) {
        float ta = (-1.0f - bv) / dv;
        float tb = (512.0f - bv) / dv;
        t0 = fmaxf(t0, fminf(ta, tb));
        t1 = fminf(t1, fmaxf(ta, tb));
    } else if (bv <= -1.0f || bv >= 512.0f) {
        t0 = 1e9f;
    }

    int klo = max(0, (int)floorf(t0 + 383.5f) - 1);       // t_k = k - 383.5
    int khi = min(NT - 1, (int)ceilf(t1 + 383.5f) + 1);

    // Warp-uniform range: avoids divergent loop trip counts. Out-of-range
    // samples clamp onto the zero border and contribute exactly 0.
    klo = __reduce_min_sync(0xffffffffu, klo);
    khi = __reduce_max_sync(0xffffffffu, khi);

    float acc = 0.0f;
    #pragma unroll 4
    for (int k = klo; k <= khi; ++k) {
        float tf = (float)k - 383.5f;
        float fu = fmaf(tf, du, bu);
        float fv = fmaf(tf, dv, bv);
        float u0 = floorf(fu);
        float v0 = floorf(fv);
        float wu = fu - u0;
        float wv = fv - v0;
        int ui = (int)u0 + 1;                 // +1: padded coords
        int vi = (int)v0 + 1;
        int u0i = min(max(ui,     0), PW - 1);
        int u1i = min(max(ui + 1, 0), PW - 1);
        int v0i = min(max(vi,     0), PW - 1);
        int v1i = min(max(vi + 1, 0), PW - 1);
        const float* r0 = buf + v0i * PW;
        const float* r1 = buf + v1i * PW;
        float p00 = __ldg(r0 + u0i);
        float p01 = __ldg(r0 + u1i);
        float p10 = __ldg(r1 + u0i);
        float p11 = __ldg(r1 + u1i);
        float top = fmaf(wu, p01 - p00, p00);
        float bot = fmaf(wu, p11 - p10, p10);
        acc += fmaf(wv, bot - top, top);
    }

    if (d < ND) sino[a * ND + d] = acc;
}

extern "C" void kernel_launch(void* const* d_in, const int* in_sizes, int n_in,
                              void* d_out, int out_size) {
    const float* x    = (const float*)d_in[0];
    const float* reco = (const float*)d_in[1];
    float* out_sino = (float*)d_out;
    float* out_reco = (float*)d_out + NA * ND;

    prep_kernel<<<(PAD_ELEMS + 255) / 256, 256>>>(x, reco, out_reco);

    dim3 grid((ND + 127) / 128, NA);
    proj_kernel<<<grid, 128>>>(out_sino);
}

// round 8
// speedup vs baseline: 2.2051x; 2.2051x over previous
#include <cuda_runtime.h>
#include <cuda_fp16.h>

// Geometry constants (match reference)
#define HN 512
#define WN 512
#define NA 720
#define ND 725
#define NT 768
#define PW 516                  // 512 + 2-px zero border each side
#define OFF 2
#define PAD_ELEMS (PW * PW)

// Quad layout: g_quad?[v*PW+u] packs the 2x2 bilinear footprint
//   (I[v][u], I[v][u+1], I[v+1][u], I[v+1][u+1])  as 4 x fp16 in a uint2.
// g_quadP: image orientation.  g_quadT: transposed orientation.
__device__ uint2 g_quadP[PAD_ELEMS];
__device__ uint2 g_quadT[PAD_ELEMS];

__device__ __forceinline__ unsigned pack_h2(float lo, float hi) {
    __half2 h = __floats2half2_rn(lo, hi);
    return *reinterpret_cast<unsigned*>(&h);
}

__device__ __forceinline__ float2 unpack_h2(unsigned w) {
    __half2 h = *reinterpret_cast<__half2*>(&w);
    return __half22float2(h);
}

__device__ __forceinline__ float padval(const float* __restrict__ x,
                                        const float* __restrict__ reco,
                                        int v, int u) {
    v -= OFF; u -= OFF;
    if ((unsigned)v < (unsigned)HN && (unsigned)u < (unsigned)WN) {
        int s = v * WN + u;
        return x[s] + reco[s];
    }
    return 0.0f;
}

__global__ void prep_kernel(const float* __restrict__ x,
                            const float* __restrict__ reco,
                            float* __restrict__ out_reco) {
    int i = blockIdx.x * blockDim.x + threadIdx.x;
    if (i >= PAD_ELEMS) return;
    int r = i / PW;
    int q = i - r * PW;

    // direct orientation
    float a00 = padval(x, reco, r,     q);
    float a01 = padval(x, reco, r,     q + 1);
    float a10 = padval(x, reco, r + 1, q);
    float a11 = padval(x, reco, r + 1, q + 1);
    uint2 qp;
    qp.x = pack_h2(a00, a01);
    qp.y = pack_h2(a10, a11);
    g_quadP[i] = qp;

    // transposed orientation: IT[v][u] = I[u][v]
    float b00 = padval(x, reco, q,     r);
    float b01 = padval(x, reco, q + 1, r);
    float b10 = padval(x, reco, q,     r + 1);
    float b11 = padval(x, reco, q + 1, r + 1);
    uint2 qt;
    qt.x = pack_h2(b00, b01);
    qt.y = pack_h2(b10, b11);
    g_quadT[i] = qt;

    if (i < HN * WN) out_reco[i] = reco[i];
}

// One thread per (angle, detector). Exact per-thread t-range; single LDG.64
// per sample fetches the whole 2x2 bilinear footprint.
__global__ void __launch_bounds__(128) proj_kernel(float* __restrict__ sino) {
    const int a = blockIdx.y;
    const int d = blockIdx.x * blockDim.x + threadIdx.x;
    if (d >= ND) return;

    const float theta = (float)a * (float)(3.14159265358979323846 / 720.0);
    float sn, c;
    sincosf(theta, &sn, &c);

    const float s = (float)d - 362.0f;      // (ND-1)/2 = 362
    // sample point: x(t) = s*c - t*sn + 255.5 ; y(t) = s*sn + t*c + 255.5
    const float bx = fmaf(s, c, 255.5f);
    const float by = fmaf(s, sn, 255.5f);

    const uint2* __restrict__ buf;
    float bu, bv, du, dv;
    if (fabsf(sn) > fabsf(c)) {              // lane axis mostly vertical -> transpose
        buf = g_quadT; bu = by; du = c;  bv = bx; dv = -sn;
    } else {
        buf = g_quadP; bu = bx; du = -sn; bv = by; dv = c;
    }

    // Clip t so fu,fv in [-1, 512] (outside => contribution exactly 0).
    // |dv| >= sqrt(2)/2 > 0 always (layout selection); du may be ~0.
    float t0, t1;
    {
        float inv = 1.0f / dv;
        float ta = (-1.0f - bv) * inv;
        float tb = (512.0f - bv) * inv;
        t0 = fminf(ta, tb);
        t1 = fmaxf(ta, tb);
    }
    if (fabsf(du) > 1e-8f) {
        float inv = 1.0f / du;
        float ta = (-1.0f - bu) * inv;
        float tb = (512.0f - bu) * inv;
        t0 = fmaxf(t0, fminf(ta, tb));
        t1 = fminf(t1, fmaxf(ta, tb));
    } else if (bu <= -1.0f || bu >= 512.0f) {
        t0 = 1.0f; t1 = 0.0f;                 // empty
    }

    // t_k = k - 383.5; tight per-thread bounds keep every active sample's
    // taps inside the 2-px-padded array without any clamping.
    int klo = max(0,      (int)ceilf(t0 + 383.5f));
    int khi = min(NT - 1, (int)floorf(t1 + 383.5f));

    float acc = 0.0f;
    #pragma unroll 4
    for (int k = klo; k <= khi; ++k) {
        float tf = (float)k - 383.5f;
        float fu = fmaf(tf, du, bu);
        float fv = fmaf(tf, dv, bv);
        float u0 = floorf(fu);
        float v0 = floorf(fv);
        float wu = fu - u0;
        float wv = fv - v0;
        int ui = (int)u0 + OFF;               // in [0, 515]
        int vi = (int)v0 + OFF;               // in [0, 515]
        uint2 qd = __ldg(buf + vi * PW + ui);
        float2 r0 = unpack_h2(qd.x);
        float2 r1 = unpack_h2(qd.y);
        float top = fmaf(wu, r0.y - r0.x, r0.x);
        float bot = fmaf(wu, r1.y - r1.x, r1.x);
        acc += fmaf(wv, bot - top, top);
    }

    sino[a * ND + d] = acc;
}

extern "C" void kernel_launch(void* const* d_in, const int* in_sizes, int n_in,
                              void* d_out, int out_size) {
    const float* x    = (const float*)d_in[0];
    const float* reco = (const float*)d_in[1];
    float* out_sino = (float*)d_out;
    float* out_reco = (float*)d_out + NA * ND;

    prep_kernel<<<(PAD_ELEMS + 255) / 256, 256>>>(x, reco, out_reco);

    dim3 grid((ND + 127) / 128, NA);
    proj_kernel<<<grid, 128>>>(out_sino);
}

// round 9
// speedup vs baseline: 2.4776x; 1.1236x over previous
#include <cuda_runtime.h>
#include <cuda_fp16.h>

// Geometry constants (match reference)
#define HN 512
#define WN 512
#define NA 720
#define ND 725
#define NT 768
#define PW 516                  // 512 + 2-px zero border each side
#define OFF 2
#define PAD_ELEMS (PW * PW)

// Quad layout (column pairs): g_quad?[v*PW+u] packs the 2x2 bilinear footprint
//   .x = (I[v][u],   I[v+1][u])    (left column,  half2)
//   .y = (I[v][u+1], I[v+1][u+1])  (right column, half2)
// so the horizontal lerp is a single half2 FMA producing (top, bottom).
__device__ uint2 g_quadP[PAD_ELEMS];
__device__ uint2 g_quadT[PAD_ELEMS];

__device__ __forceinline__ unsigned pack_h2(float lo, float hi) {
    __half2 h = __floats2half2_rn(lo, hi);
    return *reinterpret_cast<unsigned*>(&h);
}

__device__ __forceinline__ float padval(const float* __restrict__ x,
                                        const float* __restrict__ reco,
                                        int v, int u) {
    v -= OFF; u -= OFF;
    if ((unsigned)v < (unsigned)HN && (unsigned)u < (unsigned)WN) {
        int s = v * WN + u;
        return x[s] + reco[s];
    }
    return 0.0f;
}

__global__ void prep_kernel(const float* __restrict__ x,
                            const float* __restrict__ reco,
                            float* __restrict__ out_reco) {
    int i = blockIdx.x * blockDim.x + threadIdx.x;
    if (i >= PAD_ELEMS) return;
    int r = i / PW;
    int q = i - r * PW;

    // direct orientation: row r, col q
    float a00 = padval(x, reco, r,     q);
    float a01 = padval(x, reco, r,     q + 1);
    float a10 = padval(x, reco, r + 1, q);
    float a11 = padval(x, reco, r + 1, q + 1);
    uint2 qp;
    qp.x = pack_h2(a00, a10);     // left column (top, bottom)
    qp.y = pack_h2(a01, a11);     // right column (top, bottom)
    g_quadP[i] = qp;

    // transposed orientation: IT[v][u] = I[u][v]
    float b00 = padval(x, reco, q,     r);
    float b01 = padval(x, reco, q + 1, r);
    float b10 = padval(x, reco, q,     r + 1);
    float b11 = padval(x, reco, q + 1, r + 1);
    uint2 qt;
    qt.x = pack_h2(b00, b10);
    qt.y = pack_h2(b01, b11);
    g_quadT[i] = qt;

    if (i < HN * WN) out_reco[i] = reco[i];
}

// One thread per (angle, detector). Exact per-thread t-range; one LDG.64 per
// sample fetches the whole 2x2 footprint; floor via 2^23 magic (no cvt ops);
// horizontal lerp in half2.
__global__ void __launch_bounds__(128) proj_kernel(float* __restrict__ sino) {
    const int a = blockIdx.y;
    const int d = blockIdx.x * blockDim.x + threadIdx.x;
    if (d >= ND) return;

    const float theta = (float)a * (float)(3.14159265358979323846 / 720.0);
    float sn, c;
    sincosf(theta, &sn, &c);

    const float s = (float)d - 362.0f;      // (ND-1)/2 = 362
    // sample point: x(t) = s*c - t*sn + 255.5 ; y(t) = s*sn + t*c + 255.5
    const float bx = fmaf(s, c, 255.5f);
    const float by = fmaf(s, sn, 255.5f);

    const uint2* __restrict__ buf;
    float bu, bv, du, dv;
    if (fabsf(sn) > fabsf(c)) {              // lane axis mostly vertical -> transpose
        buf = g_quadT; bu = by; du = c;  bv = bx; dv = -sn;
    } else {
        buf = g_quadP; bu = bx; du = -sn; bv = by; dv = c;
    }

    // Clip t so fu,fv in [-1, 512] (outside => contribution exactly 0).
    // |dv| >= sqrt(2)/2 > 0 always (layout selection); du may be ~0.
    float t0, t1;
    {
        float inv = 1.0f / dv;
        float ta = (-1.0f - bv) * inv;
        float tb = (512.0f - bv) * inv;
        t0 = fminf(ta, tb);
        t1 = fmaxf(ta, tb);
    }
    if (fabsf(du) > 1e-8f) {
        float inv = 1.0f / du;
        float ta = (-1.0f - bu) * inv;
        float tb = (512.0f - bu) * inv;
        t0 = fmaxf(t0, fminf(ta, tb));
        t1 = fminf(t1, fmaxf(ta, tb));
    } else if (bu <= -1.0f || bu >= 512.0f) {
        t0 = 1.0f; t1 = 0.0f;                 // empty
    }

    // t_k = k - 383.5; tight per-thread bounds keep every active sample's
    // taps inside the 2-px-padded array without any clamping.
    int klo = max(0,      (int)ceilf(t0 + 383.5f));
    int khi = min(NT - 1, (int)floorf(t1 + 383.5f));

    // Bases in padded coords (fu,fv in [1-eps, 514+eps] within the loop).
    const float puB = bu + (float)OFF;
    const float pvB = bv + (float)OFF;
    const float MAGIC  = 8388608.0f;          // 2^23
    const float MAGICH = 8388607.5f;          // 2^23 - 0.5  (exactly representable)

    float acc = 0.0f;
    float tf = (float)klo - 383.5f;           // exact; stays exact under += 1.0f
    #pragma unroll 4
    for (int k = klo; k <= khi; ++k, tf += 1.0f) {
        float fu = fmaf(tf, du, puB);
        float fv = fmaf(tf, dv, pvB);
        // magic floor: fm = 2^23 + floor(f); float floor = fm - 2^23;
        // integer floor lives in the low mantissa bits.
        float fmu = fu + MAGICH;
        float fmv = fv + MAGICH;
        float wu  = fu - (fmu - MAGIC);
        float wv  = fv - (fmv - MAGIC);
        int ui = __float_as_int(fmu) - 0x4B000000;
        int vi = __float_as_int(fmv) - 0x4B000000;

        uint2 qd = __ldg(buf + vi * PW + ui);
        __half2 A = *reinterpret_cast<__half2*>(&qd.x);   // (top_l, bot_l)
        __half2 B = *reinterpret_cast<__half2*>(&qd.y);   // (top_r, bot_r)
        __half2 wu2 = __float2half2_rn(wu);
        __half2 res = __hfma2(__hsub2(B, A), wu2, A);     // (top, bottom)
        float2 rf = __half22float2(res);
        acc += fmaf(wv, rf.y - rf.x, rf.x);
    }

    sino[a * ND + d] = acc;
}

extern "C" void kernel_launch(void* const* d_in, const int* in_sizes, int n_in,
                              void* d_out, int out_size) {
    const float* x    = (const float*)d_in[0];
    const float* reco = (const float*)d_in[1];
    float* out_sino = (float*)d_out;
    float* out_reco = (float*)d_out + NA * ND;

    prep_kernel<<<(PAD_ELEMS + 255) / 256, 256>>>(x, reco, out_reco);

    dim3 grid((ND + 127) / 128, NA);
    proj_kernel<<<grid, 128>>>(out_sino);
}

// round 11
// speedup vs baseline: 2.9080x; 1.1737x over previous
#include <cuda_runtime.h>
#include <cuda_fp16.h>

// Geometry constants (match reference)
#define HN 512
#define WN 512
#define NA 720
#define ND 725
#define NT 768
#define PW 516                  // 512 + 2-px zero border each side
#define OFF 2
#define PAD_ELEMS (PW * PW)

typedef unsigned long long ull;

// Quad layout (column pairs): g_quad?[v*PW+u] packs the 2x2 bilinear footprint
//   .x = (I[v][u],   I[v+1][u])    (left column,  half2)
//   .y = (I[v][u+1], I[v+1][u+1])  (right column, half2)
__device__ uint2 g_quadP[PAD_ELEMS];
__device__ uint2 g_quadT[PAD_ELEMS];

__device__ __forceinline__ unsigned pack_h2(float lo, float hi) {
    __half2 h = __floats2half2_rn(lo, hi);
    return *reinterpret_cast<unsigned*>(&h);
}

// ---- packed f32x2 helpers (sm_103a) ----
__device__ __forceinline__ ull pk2(float lo, float hi) {
    ull r; asm("mov.b64 %0, {%1, %2};" : "=l"(r) : "f"(lo), "f"(hi)); return r;
}
__device__ __forceinline__ void upk2(float& lo, float& hi, ull v) {
    asm("mov.b64 {%0, %1}, %2;" : "=f"(lo), "=f"(hi) : "l"(v));
}
__device__ __forceinline__ ull fma2(ull a, ull b, ull c) {
    ull r; asm("fma.rn.f32x2 %0, %1, %2, %3;" : "=l"(r) : "l"(a), "l"(b), "l"(c)); return r;
}
__device__ __forceinline__ ull add2(ull a, ull b) {
    ull r; asm("add.rn.f32x2 %0, %1, %2;" : "=l"(r) : "l"(a), "l"(b)); return r;
}

__device__ __forceinline__ float padval(const float* __restrict__ x,
                                        const float* __restrict__ reco,
                                        int v, int u) {
    v -= OFF; u -= OFF;
    if ((unsigned)v < (unsigned)HN && (unsigned)u < (unsigned)WN) {
        int s = v * WN + u;
        return x[s] + reco[s];
    }
    return 0.0f;
}

__global__ void prep_kernel(const float* __restrict__ x,
                            const float* __restrict__ reco,
                            float* __restrict__ out_reco) {
    int i = blockIdx.x * blockDim.x + threadIdx.x;
    if (i >= PAD_ELEMS) return;
    int r = i / PW;
    int q = i - r * PW;

    float a00 = padval(x, reco, r,     q);
    float a01 = padval(x, reco, r,     q + 1);
    float a10 = padval(x, reco, r + 1, q);
    float a11 = padval(x, reco, r + 1, q + 1);
    uint2 qp;
    qp.x = pack_h2(a00, a10);
    qp.y = pack_h2(a01, a11);
    g_quadP[i] = qp;

    float b00 = padval(x, reco, q,     r);
    float b01 = padval(x, reco, q + 1, r);
    float b10 = padval(x, reco, q,     r + 1);
    float b11 = padval(x, reco, q + 1, r + 1);
    uint2 qt;
    qt.x = pack_h2(b00, b10);
    qt.y = pack_h2(b01, b11);
    g_quadT[i] = qt;

    if (i < HN * WN) out_reco[i] = reco[i];
}

// Warp tiling: each warp covers 8 detectors x 4 t-offsets.
//   lane = (m<<3) | j :  j = detector offset, m = t phase (stride 4).
// Block = 128 threads = 4 warps = 32 detectors, one angle per blockIdx.y.
__global__ void __launch_bounds__(128) proj_kernel(float* __restrict__ sino) {
    const int a    = blockIdx.y;
    const int tid  = threadIdx.x;
    const int warp = tid >> 5;
    const int lane = tid & 31;
    const int j    = lane & 7;
    const int m    = lane >> 3;

    const int d    = blockIdx.x * 32 + warp * 8 + j;
    const int de   = min(d, ND - 1);

    const float theta = (float)a * (float)(3.14159265358979323846 / 720.0);
    float sn, c;
    sincosf(theta, &sn, &c);

    const float s = (float)de - 362.0f;     // (ND-1)/2 = 362
    const float bx = fmaf(s, c, 255.5f);
    const float by = fmaf(s, sn, 255.5f);

    const uint2* __restrict__ buf;
    float bu, bv, du, dv;
    if (fabsf(sn) > fabsf(c)) {             // lane axis mostly vertical -> transpose
        buf = g_quadT; bu = by; du = c;  bv = bx; dv = -sn;
    } else {
        buf = g_quadP; bu = bx; du = -sn; bv = by; dv = c;
    }

    // Clip t so fu,fv in [-1, 512] (outside => contribution exactly 0).
    float t0, t1;
    {
        float inv = 1.0f / dv;              // |dv| >= sqrt(2)/2 by layout choice
        float ta = (-1.0f - bv) * inv;
        float tb = (512.0f - bv) * inv;
        t0 = fminf(ta, tb);
        t1 = fmaxf(ta, tb);
    }
    if (fabsf(du) > 1e-8f) {
        float inv = 1.0f / du;
        float ta = (-1.0f - bu) * inv;
        float tb = (512.0f - bu) * inv;
        t0 = fmaxf(t0, fminf(ta, tb));
        t1 = fminf(t1, fmaxf(ta, tb));
    } else if (bu <= -1.0f || bu >= 512.0f) {
        t0 = 1.0f; t1 = 0.0f;               // empty
    }

    // t_k = k - 383.5. (int) of an out-of-range float SATURATES on GPU; clamp
    // klo to NT so klo+m can never overflow (theta = pi/2 rays that miss the
    // image produce t0 ~ +1e10 -> klo would saturate to INT_MAX otherwise).
    int klo = max(0,      (int)ceilf(t0 + 383.5f));
    klo = min(klo, NT);
    const int khi = min(NT - 1, (int)floorf(t1 + 383.5f));

    // packed coordinate state (u in low, v in high)
    const ull duv  = pk2(du, dv);
    const ull puv  = pk2(bu + (float)OFF, bv + (float)OFF);
    const float MAGIC  = 8388608.0f;        // 2^23
    const float MAGICH = 8388607.5f;
    const ull MAG2  = pk2(MAGICH, MAGICH);
    const ull NMAG2 = pk2(-MAGIC, -MAGIC);
    const ull NONE2 = pk2(-1.0f, -1.0f);
    const ull STEP2 = pk2(4.0f, 4.0f);

    float tf0 = (float)(klo + m) - 383.5f;  // exact; stays exact under += 4.0
    ull tf2 = pk2(tf0, tf0);

    float acc = 0.0f;
    #pragma unroll 4
    for (int k = klo + m; k <= khi; k += 4) {
        ull fuv = fma2(tf2, duv, puv);
        ull fm2 = add2(fuv, MAG2);          // 2^23 + floor(f) in each half
        ull fl2 = add2(fm2, NMAG2);         // float floor
        ull w2  = fma2(fl2, NONE2, fuv);    // fractional parts (wu, wv)
        tf2 = add2(tf2, STEP2);

        float fmu, fmv; upk2(fmu, fmv, fm2);
        // mask+clamp: any edge-case floor (incl. negative -> high mask value)
        // lands on index 515, whose quad is exactly zero (border), so the
        // contribution is 0 -- identical to reference out-of-range masking.
        int ui = min(__float_as_int(fmu) & 0xFFF, PW - 1);
        int vi = min(__float_as_int(fmv) & 0xFFF, PW - 1);
        float wu, wv; upk2(wu, wv, w2);

        uint2 qd = __ldg(buf + vi * PW + ui);
        __half2 A = *reinterpret_cast<__half2*>(&qd.x);   // (top_l, bot_l)
        __half2 B = *reinterpret_cast<__half2*>(&qd.y);   // (top_r, bot_r)
        __half2 wu2 = __float2half2_rn(wu);
        __half2 res = __hfma2(__hsub2(B, A), wu2, A);     // (top, bottom)
        float2 rf = __half22float2(res);
        acc += fmaf(wv, rf.y - rf.x, rf.x);
    }

    // reduce the 4 t-phases of each detector
    acc += __shfl_xor_sync(0xffffffffu, acc, 8);
    acc += __shfl_xor_sync(0xffffffffu, acc, 16);

    if (m == 0 && d < ND) sino[a * ND + d] = acc;
}

extern "C" void kernel_launch(void* const* d_in, const int* in_sizes, int n_in,
                              void* d_out, int out_size) {
    const float* x    = (const float*)d_in[0];
    const float* reco = (const float*)d_in[1];
    float* out_sino = (float*)d_out;
    float* out_reco = (float*)d_out + NA * ND;

    prep_kernel<<<(PAD_ELEMS + 255) / 256, 256>>>(x, reco, out_reco);

    dim3 grid((ND + 31) / 32, NA);
    proj_kernel<<<grid, 128>>>(out_sino);
}